// round 16
// baseline (speedup 1.0000x reference)
#include <cuda_runtime.h>
#include <cstdint>

// Elementwise ReLU, HBM-bound. 2^27 fp32 = 1 GiB traffic.
//
// Per-thread-work sweep (kernel us / DRAM%):
//   grid-stride ~110 f4 : ~164 / 78.5   (long-CTA spread penalty)
//   flat 1 f4           : 156.8 / 82.0
//   flat 2 f4           : 149.9 / 85.7
//   flat 4 f4           : 149.1 / 86.1
// This round completes the sweep: flat 8 f4 (16384 CTAs, 32KB/CTA,
// 8 front-batched independent LDG.128 -> deep MLP, one burst then exit).
// Load via __ldg, store evict-first (.cs) (established best policy).
// (R15 was an infra failure — resubmitting unchanged.)

__global__ __launch_bounds__(256) void relu_flat8_kernel(
    const float4* __restrict__ in, float4* __restrict__ out, int n4)
{
    const int bd = blockDim.x;
    int base = blockIdx.x * (bd * 8) + threadIdx.x;

    if (base + 7 * bd < n4) {
        // Fast path (always taken for this problem's 2^25 f4 / 2048-per-CTA split).
        float4 v0 = __ldg(&in[base]);
        float4 v1 = __ldg(&in[base + bd]);
        float4 v2 = __ldg(&in[base + 2 * bd]);
        float4 v3 = __ldg(&in[base + 3 * bd]);
        float4 v4 = __ldg(&in[base + 4 * bd]);
        float4 v5 = __ldg(&in[base + 5 * bd]);
        float4 v6 = __ldg(&in[base + 6 * bd]);
        float4 v7 = __ldg(&in[base + 7 * bd]);
        v0.x = fmaxf(v0.x, 0.f); v0.y = fmaxf(v0.y, 0.f); v0.z = fmaxf(v0.z, 0.f); v0.w = fmaxf(v0.w, 0.f);
        v1.x = fmaxf(v1.x, 0.f); v1.y = fmaxf(v1.y, 0.f); v1.z = fmaxf(v1.z, 0.f); v1.w = fmaxf(v1.w, 0.f);
        v2.x = fmaxf(v2.x, 0.f); v2.y = fmaxf(v2.y, 0.f); v2.z = fmaxf(v2.z, 0.f); v2.w = fmaxf(v2.w, 0.f);
        v3.x = fmaxf(v3.x, 0.f); v3.y = fmaxf(v3.y, 0.f); v3.z = fmaxf(v3.z, 0.f); v3.w = fmaxf(v3.w, 0.f);
        v4.x = fmaxf(v4.x, 0.f); v4.y = fmaxf(v4.y, 0.f); v4.z = fmaxf(v4.z, 0.f); v4.w = fmaxf(v4.w, 0.f);
        v5.x = fmaxf(v5.x, 0.f); v5.y = fmaxf(v5.y, 0.f); v5.z = fmaxf(v5.z, 0.f); v5.w = fmaxf(v5.w, 0.f);
        v6.x = fmaxf(v6.x, 0.f); v6.y = fmaxf(v6.y, 0.f); v6.z = fmaxf(v6.z, 0.f); v6.w = fmaxf(v6.w, 0.f);
        v7.x = fmaxf(v7.x, 0.f); v7.y = fmaxf(v7.y, 0.f); v7.z = fmaxf(v7.z, 0.f); v7.w = fmaxf(v7.w, 0.f);
        __stcs(&out[base],          v0);
        __stcs(&out[base + bd],     v1);
        __stcs(&out[base + 2 * bd], v2);
        __stcs(&out[base + 3 * bd], v3);
        __stcs(&out[base + 4 * bd], v4);
        __stcs(&out[base + 5 * bd], v5);
        __stcs(&out[base + 6 * bd], v6);
        __stcs(&out[base + 7 * bd], v7);
    } else {
        #pragma unroll
        for (int k = 0; k < 8; k++) {
            int i = base + k * bd;
            if (i < n4) {
                float4 a = __ldg(&in[i]);
                a.x = fmaxf(a.x, 0.f); a.y = fmaxf(a.y, 0.f);
                a.z = fmaxf(a.z, 0.f); a.w = fmaxf(a.w, 0.f);
                __stcs(&out[i], a);
            }
        }
    }
}

__global__ __launch_bounds__(256) void relu_scalar_kernel(
    const float* __restrict__ in, float* __restrict__ out, int n, int start)
{
    int i = start + blockIdx.x * blockDim.x + threadIdx.x;
    if (i < n) out[i] = fmaxf(__ldg(&in[i]), 0.f);
}

extern "C" void kernel_launch(void* const* d_in, const int* in_sizes, int n_in,
                              void* d_out, int out_size)
{
    const float* in = (const float*)d_in[0];
    float* out = (float*)d_out;
    int n = in_sizes[0];

    int n4 = n / 4;          // 2^25 here
    if (n4 > 0) {
        const int threads = 256;
        const int per_cta = threads * 8;
        int blocks = (n4 + per_cta - 1) / per_cta;   // 16384
        relu_flat8_kernel<<<blocks, threads>>>(
            (const float4*)in, (float4*)out, n4);
    }
    int rem = n - n4 * 4;
    if (rem > 0) {
        relu_scalar_kernel<<<(rem + 255) / 256, 256>>>(in, out, n, n4 * 4);
    }
}

// round 17
// speedup vs baseline: 1.0096x; 1.0096x over previous
#include <cuda_runtime.h>
#include <cstdint>

// Elementwise ReLU, HBM-bound. 2^27 fp32 = 1 GiB traffic.
//
// Per-thread-work sweep at block=256 (kernel us / DRAM%):
//   flat 1 f4 (131072 CTAs, 4KB)  : 156.8 / 82.0
//   flat 2 f4 ( 65536 CTAs, 8KB)  : 149.9 / 85.7
//   flat 4 f4 ( 32768 CTAs, 16KB) : 149.1 / 86.1   <- best
//   flat 8 f4 ( 16384 CTAs, 32KB) : 152.3 / 84.4   (turned over)
// This round: flat4 @ block=128 -> 8KB/CTA, 65536 CTAs. Combines flat2's
// fine CTA granularity (best scheduler balance) with flat4's MLP_p1=4
// (best per-thread load batching). Load __ldg, store .cs (established).

__global__ __launch_bounds__(128) void relu_flat4_b128_kernel(
    const float4* __restrict__ in, float4* __restrict__ out, int n4)
{
    const int bd = blockDim.x;   // 128
    int base = blockIdx.x * (bd * 4) + threadIdx.x;
    int i0 = base;
    int i1 = base + bd;
    int i2 = base + 2 * bd;
    int i3 = base + 3 * bd;

    if (i3 < n4) {
        // Fast path: always taken for this problem (2^25 f4, 512 f4/CTA).
        float4 a = __ldg(&in[i0]);
        float4 b = __ldg(&in[i1]);
        float4 c = __ldg(&in[i2]);
        float4 d = __ldg(&in[i3]);
        a.x = fmaxf(a.x, 0.f); a.y = fmaxf(a.y, 0.f); a.z = fmaxf(a.z, 0.f); a.w = fmaxf(a.w, 0.f);
        b.x = fmaxf(b.x, 0.f); b.y = fmaxf(b.y, 0.f); b.z = fmaxf(b.z, 0.f); b.w = fmaxf(b.w, 0.f);
        c.x = fmaxf(c.x, 0.f); c.y = fmaxf(c.y, 0.f); c.z = fmaxf(c.z, 0.f); c.w = fmaxf(c.w, 0.f);
        d.x = fmaxf(d.x, 0.f); d.y = fmaxf(d.y, 0.f); d.z = fmaxf(d.z, 0.f); d.w = fmaxf(d.w, 0.f);
        __stcs(&out[i0], a);
        __stcs(&out[i1], b);
        __stcs(&out[i2], c);
        __stcs(&out[i3], d);
    } else {
        #pragma unroll
        for (int k = 0; k < 4; k++) {
            int i = base + k * bd;
            if (i < n4) {
                float4 a = __ldg(&in[i]);
                a.x = fmaxf(a.x, 0.f); a.y = fmaxf(a.y, 0.f);
                a.z = fmaxf(a.z, 0.f); a.w = fmaxf(a.w, 0.f);
                __stcs(&out[i], a);
            }
        }
    }
}

__global__ __launch_bounds__(256) void relu_scalar_kernel(
    const float* __restrict__ in, float* __restrict__ out, int n, int start)
{
    int i = start + blockIdx.x * blockDim.x + threadIdx.x;
    if (i < n) out[i] = fmaxf(__ldg(&in[i]), 0.f);
}

extern "C" void kernel_launch(void* const* d_in, const int* in_sizes, int n_in,
                              void* d_out, int out_size)
{
    const float* in = (const float*)d_in[0];
    float* out = (float*)d_out;
    int n = in_sizes[0];

    int n4 = n / 4;          // 2^25 here
    if (n4 > 0) {
        const int threads = 128;
        const int per_cta = threads * 4;           // 512 f4 = 8KB
        int blocks = (n4 + per_cta - 1) / per_cta; // 65536
        relu_flat4_b128_kernel<<<blocks, threads>>>(
            (const float4*)in, (float4*)out, n4);
    }
    int rem = n - n4 * 4;
    if (rem > 0) {
        relu_scalar_kernel<<<(rem + 255) / 256, 256>>>(in, out, n, n4 * 4);
    }
}